// round 13
// baseline (speedup 1.0000x reference)
#include <cuda_runtime.h>
#include <cuda_bf16.h>
#include <stdint.h>

#define BB 32
#define TT 1024
#define CC 384
#define HH 64

typedef __nv_bfloat16 bf16;

// Split bf16 scratch (device globals; no allocs).
// Weights fused: [n=192][k=384]; Wq pre-scaled by 0.125*log2(e) (exp2 softmax).
__device__ bf16 g_wthi[192*CC], g_wtlo[192*CC];
__device__ bf16 g_qhi[BB*TT*HH], g_qlo[BB*TT*HH];
__device__ bf16 g_khi[BB*TT*HH], g_klo[BB*TT*HH];
__device__ bf16 g_vthi[BB*HH*TT], g_vtlo[BB*HH*TT];   // [b][h][t]

// ---------------------------------------------------------------------------
__device__ __forceinline__ void mma16816(float d[4], const uint32_t a[4],
                                         const uint32_t b[2])
{
    asm volatile(
        "mma.sync.aligned.m16n8k16.row.col.f32.bf16.bf16.f32 "
        "{%0,%1,%2,%3}, {%4,%5,%6,%7}, {%8,%9}, {%0,%1,%2,%3};"
        : "+f"(d[0]), "+f"(d[1]), "+f"(d[2]), "+f"(d[3])
        : "r"(a[0]), "r"(a[1]), "r"(a[2]), "r"(a[3]), "r"(b[0]), "r"(b[1]));
}

__device__ __forceinline__ void split2f(float v0, float v1,
                                        uint32_t& hi, uint32_t& lo)
{
    uint32_t h;
    asm("cvt.rn.bf16x2.f32 %0, %1, %2;" : "=r"(h) : "f"(v1), "f"(v0));
    float r0 = v0 - __uint_as_float(h << 16);
    float r1 = v1 - __uint_as_float(h & 0xffff0000u);
    uint32_t l;
    asm("cvt.rn.bf16x2.f32 %0, %1, %2;" : "=r"(l) : "f"(r1), "f"(r0));
    hi = h; lo = l;
}

__device__ __forceinline__ float ex2(float x)
{
    float y;
    asm("ex2.approx.ftz.f32 %0, %1;" : "=f"(y) : "f"(x));
    return y;
}

__device__ __forceinline__ void cp16(uint32_t sa, const void* g)
{
    asm volatile("cp.async.cg.shared.global [%0], [%1], 16;"
                 :: "r"(sa), "l"(g) : "memory");
}
#define CP_COMMIT() asm volatile("cp.async.commit_group;" ::: "memory")
#define CP_WAIT(n)  asm volatile("cp.async.wait_group %0;" :: "n"(n) : "memory")

__device__ __forceinline__ void ldsm4(uint32_t r[4], uint32_t addr)
{
    asm volatile("ldmatrix.sync.aligned.m8n8.x4.shared.b16 {%0,%1,%2,%3}, [%4];"
                 : "=r"(r[0]), "=r"(r[1]), "=r"(r[2]), "=r"(r[3]) : "r"(addr));
}

// ---------------------------------------------------------------------------
// Kernel A: split + transpose W -> fused [192][384].
// Wq scale = 0.125 * log2(e) so attention can use exp2 directly.
// ---------------------------------------------------------------------------
__global__ __launch_bounds__(256) void splitw_kernel(const float* __restrict__ Wk,
                                                     const float* __restrict__ Wq,
                                                     const float* __restrict__ Wv)
{
    int c = blockIdx.x * 256 + threadIdx.x;     // 0 .. 36863
    int n = c & 63;
    int rest = c >> 6;
    int kp = rest % 192;
    int w = rest / 192;                          // 0=K, 1=Q, 2=V
    const float* W = (w == 0) ? Wk : (w == 1) ? Wq : Wv;
    float sc = (w == 1) ? 0.18033688011112042f : 1.0f;   // 0.125*log2(e)
    float v0 = W[(size_t)(2 * kp) * HH + n] * sc;
    float v1 = W[(size_t)(2 * kp + 1) * HH + n] * sc;
    uint32_t hi, lo;
    split2f(v0, v1, hi, lo);
    size_t o = ((size_t)w * 64 + n) * CC + 2 * kp;
    *(uint32_t*)&g_wthi[o] = hi;
    *(uint32_t*)&g_wtlo[o] = lo;
}

// ---------------------------------------------------------------------------
// Kernel B: fused QKV projection, cp.async double-buffered, ldmatrix frags.
// ---------------------------------------------------------------------------
#define QKV_STG 40960
#define QKV_SMEM (2 * QKV_STG)
#define QX_H 0
#define QX_L 5120
#define QW_H 10240
#define QW_L 25600

__global__ __launch_bounds__(256, 2) void qkv_kernel(const float* __restrict__ x)
{
    extern __shared__ __align__(16) char qsm[];
    const uint32_t sb = (uint32_t)__cvta_generic_to_shared(qsm);

    const int tid = threadIdx.x, w = tid >> 5, lane = tid & 31;
    const int g = lane >> 2, t = lane & 3;
    const int rowbase = blockIdx.x * 64;
    const int rg = (w & 3) * 16;
    const int cg = (w >> 2) * 96;

    const int arow = ((lane >> 3) & 1) * 8 + (lane & 7);
    const int acol = (lane >> 4) & 1;
    const int brow = ((lane >> 4) & 1) * 8 + (lane & 7);
    const int bcol = (lane >> 3) & 1;
    const uint32_t aoff = (uint32_t)((rg + arow) * 80 + acol * 16);
    const uint32_t boff = (uint32_t)((cg + brow) * 80 + bcol * 16);

    const int xr = tid >> 2, xc8 = (tid & 3) * 8;
    const float* xrow = x + (size_t)(rowbase + xr) * CC + xc8;

    auto cpW = [&](int kb, int s) {
        uint32_t base = sb + s * QKV_STG;
#pragma unroll
        for (int it = 0; it < 3; it++) {
            int idx = tid + it * 256;
            int r = idx >> 2, c = idx & 3;
            cp16(base + QW_H + r * 80 + c * 16, g_wthi + (size_t)r * CC + kb * 32 + c * 8);
            cp16(base + QW_L + r * 80 + c * 16, g_wtlo + (size_t)r * CC + kb * 32 + c * 8);
        }
        CP_COMMIT();
    };
    auto stX = [&](int s, float4 v0, float4 v1) {
        uint32_t h01, l01, h23, l23, h45, l45, h67, l67;
        split2f(v0.x, v0.y, h01, l01);
        split2f(v0.z, v0.w, h23, l23);
        split2f(v1.x, v1.y, h45, l45);
        split2f(v1.z, v1.w, h67, l67);
        char* p = qsm + s * QKV_STG;
        *(uint4*)(p + QX_H + xr * 80 + xc8 * 2) = make_uint4(h01, h23, h45, h67);
        *(uint4*)(p + QX_L + xr * 80 + xc8 * 2) = make_uint4(l01, l23, l45, l67);
    };

    float acc[12][4];
#pragma unroll
    for (int i = 0; i < 12; i++)
#pragma unroll
        for (int j = 0; j < 4; j++) acc[i][j] = 0.0f;

    cpW(0, 0);
    float4 nv0 = *(const float4*)(xrow);
    float4 nv1 = *(const float4*)(xrow + 4);
    stX(0, nv0, nv1);
    nv0 = *(const float4*)(xrow + 32);
    nv1 = *(const float4*)(xrow + 36);

    for (int kb = 0; kb < 12; kb++) {
        const int s = kb & 1;
        __syncthreads();
        if (kb < 11) {
            stX(s ^ 1, nv0, nv1);
            cpW(kb + 1, s ^ 1);
            if (kb < 10) {
                nv0 = *(const float4*)(xrow + (kb + 2) * 32);
                nv1 = *(const float4*)(xrow + (kb + 2) * 32 + 4);
            }
            CP_WAIT(1);
        } else {
            CP_WAIT(0);
        }
        __syncthreads();

        const uint32_t st = sb + s * QKV_STG;
#pragma unroll
        for (int k2 = 0; k2 < 2; k2++) {
            uint32_t ah[4], al[4];
            ldsm4(ah, st + QX_H + aoff + k2 * 32);
            ldsm4(al, st + QX_L + aoff + k2 * 32);
#pragma unroll
            for (int p = 0; p < 6; p++) {
                uint32_t bh4[4], bl4[4];
                ldsm4(bh4, st + QW_H + boff + p * 1280 + k2 * 32);
                ldsm4(bl4, st + QW_L + boff + p * 1280 + k2 * 32);
                mma16816(acc[2 * p],     ah, bh4 + 0);
                mma16816(acc[2 * p],     al, bh4 + 0);
                mma16816(acc[2 * p],     ah, bl4 + 0);
                mma16816(acc[2 * p + 1], ah, bh4 + 2);
                mma16816(acc[2 * p + 1], al, bh4 + 2);
                mma16816(acc[2 * p + 1], ah, bl4 + 2);
            }
        }
    }

    const int r0 = rowbase + rg + g;
    const int bidx = r0 >> 10;
    const int t0 = r0 & (TT - 1);
#pragma unroll
    for (int nt = 0; nt < 12; nt++) {
        int col = cg + nt * 8 + 2 * t;
        int m = col >> 6, cm = col & 63;
        if (m == 2) {
#pragma unroll
            for (int jj = 0; jj < 2; jj++) {
                float v0 = acc[nt][jj];
                float v1 = acc[nt][2 + jj];
                size_t o = ((size_t)bidx * HH + cm + jj) * TT + t0;
                bf16 h0 = __float2bfloat16(v0);
                bf16 h1 = __float2bfloat16(v1);
                g_vthi[o]     = h0;
                g_vtlo[o]     = __float2bfloat16(v0 - __bfloat162float(h0));
                g_vthi[o + 8] = h1;
                g_vtlo[o + 8] = __float2bfloat16(v1 - __bfloat162float(h1));
            }
        } else {
            bf16* dh = (m == 1) ? g_qhi : g_khi;
            bf16* dl = (m == 1) ? g_qlo : g_klo;
            uint32_t h01, l01, h23, l23;
            split2f(acc[nt][0], acc[nt][1], h01, l01);
            split2f(acc[nt][2], acc[nt][3], h23, l23);
            *(uint32_t*)&dh[(size_t)r0 * HH + cm]       = h01;
            *(uint32_t*)&dl[(size_t)r0 * HH + cm]       = l01;
            *(uint32_t*)&dh[(size_t)(r0 + 8) * HH + cm] = h23;
            *(uint32_t*)&dl[(size_t)(r0 + 8) * HH + cm] = l23;
        }
    }
}

// ---------------------------------------------------------------------------
// Kernel C: flash attention, 128-query CTAs.  256 threads / 8 warps (16 rows
// each), 2 CTAs/SM (48KB smem, 128 regs).  K double-buffered, V single.
// Tile-iterations halved vs 64-q CTAs: one K/V tile + barrier-triple serves
// 2x MMA work.  Per-warp diagonal tile kt_d = 2q + (w>>2): full tiles below,
// causal-skip (pmax=(w&3)+1) on it, idle after.  exp2 softmax.
// bid->(q,b) map pairs heavy+light CTAs per SM ({s, s+148} co-residency);
// solo SMs (bids 108..147) carry the q=7/q=6 CTAs.
// ---------------------------------------------------------------------------
#define ATTN_SMEM 49152

__global__ __launch_bounds__(256, 2) void attn_kernel(float* __restrict__ out)
{
    extern __shared__ __align__(16) char asm_[];
    const uint32_t sbase = (uint32_t)__cvta_generic_to_shared(asm_);

    const int tid = threadIdx.x, w = tid >> 5, lane = tid & 31;
    const int g = lane >> 2, t = lane & 3;

    // bid -> (q, b): heavy/light pairing under {s, s+148} co-residency.
    int q, b;
    {
        int i = blockIdx.x;
        if (i >= 108 && i < 148) {
            int j = i - 108;
            q = (j < 32) ? 7 : 6;
            b = (j < 32) ? j : j - 32;
        }
        else if (i < 24)  { q = 6; b = 8 + i; }
        else if (i < 56)  { q = 5; b = i - 24; }
        else if (i < 88)  { q = 4; b = i - 56; }
        else if (i < 104) { q = 3; b = i - 88; }
        else if (i < 108) { q = 0; b = i - 104; }
        else if (i < 172) { q = 0; b = 4 + (i - 148); }
        else if (i < 204) { q = 1; b = i - 172; }
        else if (i < 236) { q = 2; b = i - 204; }
        else if (i < 252) { q = 3; b = 16 + (i - 236); }
        else              { q = 0; b = 28 + (i - 252); }
    }
    const int qrow = q * 128 + w * 16 + g;
    const int kt_d = 2 * q + (w >> 2);          // this warp's diagonal key tile
    const int ww = w & 3;
    const int nkt = 2 * q + 2;

    const int brow = ((lane >> 4) & 1) * 8 + (lane & 7);
    const int bcol = (lane >> 3) & 1;
    const int brm  = brow & 7;
    uint32_t xoff[4];
#pragma unroll
    for (int k2 = 0; k2 < 4; k2++)
        xoff[k2] = (uint32_t)(((k2 * 2 + bcol) ^ brm) << 4);
    const uint32_t rowb = (uint32_t)(brow * 128);

    const bf16* kbh = g_khi + (size_t)b * TT * HH;
    const bf16* kbl = g_klo + (size_t)b * TT * HH;
    const bf16* vbh = g_vthi + (size_t)b * HH * TT;
    const bf16* vbl = g_vtlo + (size_t)b * HH * TT;

    auto issueK = [&](int kt, int s) {
        const uint32_t st = sbase + s * 16384;
#pragma unroll
        for (int it = 0; it < 2; it++) {
            int idx = tid + it * 256;
            int r = idx >> 3, cc = idx & 7;
            uint32_t d = (uint32_t)(r * 128 + (((cc ^ (r & 7)) << 4)));
            cp16(st + d,        kbh + (size_t)kt * 4096 + idx * 8);
            cp16(st + 8192 + d, kbl + (size_t)kt * 4096 + idx * 8);
        }
        CP_COMMIT();
    };
    auto issueV = [&](int kt) {
        const uint32_t st = sbase + 32768;
#pragma unroll
        for (int it = 0; it < 2; it++) {
            int idx = tid + it * 256;
            int r = idx >> 3, cc = idx & 7;
            uint32_t d = (uint32_t)(r * 128 + (((cc ^ (r & 7)) << 4)));
            cp16(st + d,        vbh + (size_t)r * TT + kt * 64 + cc * 8);
            cp16(st + 8192 + d, vbl + (size_t)r * TT + kt * 64 + cc * 8);
        }
        CP_COMMIT();
    };

    issueK(0, 0);
    issueV(0);

    uint32_t qh[4][4], ql[4][4];
    {
        const bf16* qph = g_qhi + ((size_t)b * TT + q * 128 + w * 16) * HH;
        const bf16* qpl = g_qlo + ((size_t)b * TT + q * 128 + w * 16) * HH;
#pragma unroll
        for (int k2 = 0; k2 < 4; k2++) {
            int kc = k2 * 16 + 2 * t;
            qh[k2][0] = *(const uint32_t*)(qph + (size_t)g * HH + kc);
            qh[k2][1] = *(const uint32_t*)(qph + (size_t)(g + 8) * HH + kc);
            qh[k2][2] = *(const uint32_t*)(qph + (size_t)g * HH + kc + 8);
            qh[k2][3] = *(const uint32_t*)(qph + (size_t)(g + 8) * HH + kc + 8);
            ql[k2][0] = *(const uint32_t*)(qpl + (size_t)g * HH + kc);
            ql[k2][1] = *(const uint32_t*)(qpl + (size_t)(g + 8) * HH + kc);
            ql[k2][2] = *(const uint32_t*)(qpl + (size_t)g * HH + kc + 8);
            ql[k2][3] = *(const uint32_t*)(qpl + (size_t)(g + 8) * HH + kc + 8);
        }
    }

    float oacc[8][4];
#pragma unroll
    for (int i = 0; i < 8; i++)
#pragma unroll
        for (int j = 0; j < 4; j++) oacc[i][j] = 0.0f;
    float ls0 = 0.0f, ls1 = 0.0f;

    // One key-chunk: exp + optional boundary mask + pack P + PV MMAs.
    auto pv_chunk = [&](float sacc[8][4], int kv, int col0,
                        uint32_t stV, uint32_t stVl, bool mask) {
        uint32_t ph[4], pl[4];
#pragma unroll
        for (int j = 0; j < 2; j++) {
            int nt = 2 * kv + j;
            float e0, e1, e2, e3;
            if (mask) {
                int c0 = col0 + nt * 8;
                e0 = (c0     <= qrow)     ? ex2(sacc[nt][0]) : 0.0f;
                e1 = (c0 + 1 <= qrow)     ? ex2(sacc[nt][1]) : 0.0f;
                e2 = (c0     <= qrow + 8) ? ex2(sacc[nt][2]) : 0.0f;
                e3 = (c0 + 1 <= qrow + 8) ? ex2(sacc[nt][3]) : 0.0f;
            } else {
                e0 = ex2(sacc[nt][0]);
                e1 = ex2(sacc[nt][1]);
                e2 = ex2(sacc[nt][2]);
                e3 = ex2(sacc[nt][3]);
            }
            ls0 += e0 + e1;
            ls1 += e2 + e3;
            uint32_t h01, l01, h23, l23;
            split2f(e0, e1, h01, l01);
            split2f(e2, e3, h23, l23);
            ph[j * 2]     = h01;
            ph[j * 2 + 1] = h23;
            pl[j * 2]     = l01;
            pl[j * 2 + 1] = l23;
        }
#pragma unroll
        for (int p = 0; p < 4; p++) {
            uint32_t bh4[4], bl4[4];
            ldsm4(bh4, stV  + p * 2048 + xoff[kv]);
            ldsm4(bl4, stVl + p * 2048 + xoff[kv]);
            mma16816(oacc[2 * p],     ph, bh4 + 0);
            mma16816(oacc[2 * p],     pl, bh4 + 0);
            mma16816(oacc[2 * p],     ph, bl4 + 0);
            mma16816(oacc[2 * p + 1], ph, bh4 + 2);
            mma16816(oacc[2 * p + 1], pl, bh4 + 2);
            mma16816(oacc[2 * p + 1], ph, bl4 + 2);
        }
    };

    const uint32_t stVb  = sbase + 32768 + rowb;
    const uint32_t stVlb = stVb + 8192;

    for (int kt = 0; kt < nkt; kt++) {
        const int s = kt & 1;
        if (kt > 0) {
            __syncthreads();            // B1: PV(kt-1) reads done -> V free
            issueV(kt);
        }
        if (kt < nkt - 1) {
            issueK(kt + 1, s ^ 1);
            CP_WAIT(2);                 // K(kt) landed
        } else {
            CP_WAIT(1);
        }
        __syncthreads();                // B2: K(kt) visible

        const uint32_t stK  = sbase + s * 16384 + rowb;
        const uint32_t stKl = stK + 8192;

        float sacc[8][4];
#pragma unroll
        for (int i = 0; i < 8; i++)
#pragma unroll
            for (int j = 0; j < 4; j++) sacc[i][j] = 0.0f;

        if (kt < kt_d) {
            // Full tile: unrolled 4x4.
#pragma unroll
            for (int k2 = 0; k2 < 4; k2++) {
#pragma unroll
                for (int p = 0; p < 4; p++) {
                    uint32_t bh4[4], bl4[4];
                    ldsm4(bh4, stK  + p * 2048 + xoff[k2]);
                    ldsm4(bl4, stKl + p * 2048 + xoff[k2]);
                    mma16816(sacc[2 * p],     qh[k2], bh4 + 0);
                    mma16816(sacc[2 * p],     ql[k2], bh4 + 0);
                    mma16816(sacc[2 * p],     qh[k2], bl4 + 0);
                    mma16816(sacc[2 * p + 1], qh[k2], bh4 + 2);
                    mma16816(sacc[2 * p + 1], ql[k2], bh4 + 2);
                    mma16816(sacc[2 * p + 1], qh[k2], bl4 + 2);
                }
            }
        } else if (kt == kt_d) {
            // Diagonal tile for this warp: only key groups p <= ww needed.
#pragma unroll
            for (int k2 = 0; k2 < 4; k2++) {
                for (int p = 0; p <= ww; p++) {
                    uint32_t bh4[4], bl4[4];
                    ldsm4(bh4, stK  + p * 2048 + xoff[k2]);
                    ldsm4(bl4, stKl + p * 2048 + xoff[k2]);
                    mma16816(sacc[2 * p],     qh[k2], bh4 + 0);
                    mma16816(sacc[2 * p],     ql[k2], bh4 + 0);
                    mma16816(sacc[2 * p],     qh[k2], bl4 + 0);
                    mma16816(sacc[2 * p + 1], qh[k2], bh4 + 2);
                    mma16816(sacc[2 * p + 1], ql[k2], bh4 + 2);
                    mma16816(sacc[2 * p + 1], qh[k2], bl4 + 2);
                }
            }
        }
        // kt > kt_d: this warp is fully masked; nothing to compute.

        if (kt < nkt - 1) CP_WAIT(1);   // V(kt) landed (K(kt+1) in flight)
        else              CP_WAIT(0);
        __syncthreads();                // B3: V(kt) visible

        const int col0 = kt * 64 + 2 * t;
        if (kt < kt_d) {
#pragma unroll
            for (int kv = 0; kv < 4; kv++)
                pv_chunk(sacc, kv, col0, stVb, stVlb, false);
        } else if (kt == kt_d) {
            for (int kv = 0; kv <= ww; kv++)
                pv_chunk(sacc, kv, col0, stVb, stVlb, kv == ww);
        }
    }

    ls0 += __shfl_xor_sync(0xffffffffu, ls0, 1);
    ls0 += __shfl_xor_sync(0xffffffffu, ls0, 2);
    ls1 += __shfl_xor_sync(0xffffffffu, ls1, 1);
    ls1 += __shfl_xor_sync(0xffffffffu, ls1, 2);
    float i0 = 1.0f / ls0, i1 = 1.0f / ls1;

    float* op = out + ((size_t)b * TT + qrow) * HH;
#pragma unroll
    for (int nt = 0; nt < 8; nt++) {
        int col = nt * 8 + 2 * t;
        *(float2*)(op + col)          = make_float2(oacc[nt][0] * i0, oacc[nt][1] * i0);
        *(float2*)(op + 8 * HH + col) = make_float2(oacc[nt][2] * i1, oacc[nt][3] * i1);
    }
}

// ---------------------------------------------------------------------------
extern "C" void kernel_launch(void* const* d_in, const int* in_sizes, int n_in,
                              void* d_out, int out_size)
{
    const float* x  = (const float*)d_in[0];
    const float* Wk = (const float*)d_in[1];
    const float* Wq = (const float*)d_in[2];
    const float* Wv = (const float*)d_in[3];
    float* out = (float*)d_out;
    (void)in_sizes; (void)n_in; (void)out_size;

    splitw_kernel<<<144, 256>>>(Wk, Wq, Wv);

    cudaFuncSetAttribute(qkv_kernel,
                         cudaFuncAttributeMaxDynamicSharedMemorySize,
                         QKV_SMEM);
    qkv_kernel<<<BB * TT / 64, 256, QKV_SMEM>>>(x);

    cudaFuncSetAttribute(attn_kernel,
                         cudaFuncAttributeMaxDynamicSharedMemorySize,
                         ATTN_SMEM);
    attn_kernel<<<256, 256, ATTN_SMEM>>>(out);
}

// round 14
// speedup vs baseline: 1.0546x; 1.0546x over previous
#include <cuda_runtime.h>
#include <cuda_bf16.h>
#include <stdint.h>

#define BB 32
#define TT 1024
#define CC 384
#define HH 64

typedef __nv_bfloat16 bf16;

// Split bf16 scratch (device globals; no allocs).
// Weights fused: [n=192][k=384]; Wq pre-scaled by 0.125*log2(e) (exp2 softmax).
__device__ bf16 g_wthi[192*CC], g_wtlo[192*CC];
__device__ bf16 g_qhi[BB*TT*HH], g_qlo[BB*TT*HH];
__device__ bf16 g_khi[BB*TT*HH], g_klo[BB*TT*HH];
__device__ bf16 g_vthi[BB*HH*TT], g_vtlo[BB*HH*TT];   // [b][h][t]
__device__ int  g_qkv_ctr;                             // persistent-qkv tile counter

// ---------------------------------------------------------------------------
__device__ __forceinline__ void mma16816(float d[4], const uint32_t a[4],
                                         const uint32_t b[2])
{
    asm volatile(
        "mma.sync.aligned.m16n8k16.row.col.f32.bf16.bf16.f32 "
        "{%0,%1,%2,%3}, {%4,%5,%6,%7}, {%8,%9}, {%0,%1,%2,%3};"
        : "+f"(d[0]), "+f"(d[1]), "+f"(d[2]), "+f"(d[3])
        : "r"(a[0]), "r"(a[1]), "r"(a[2]), "r"(a[3]), "r"(b[0]), "r"(b[1]));
}

__device__ __forceinline__ void split2f(float v0, float v1,
                                        uint32_t& hi, uint32_t& lo)
{
    uint32_t h;
    asm("cvt.rn.bf16x2.f32 %0, %1, %2;" : "=r"(h) : "f"(v1), "f"(v0));
    float r0 = v0 - __uint_as_float(h << 16);
    float r1 = v1 - __uint_as_float(h & 0xffff0000u);
    uint32_t l;
    asm("cvt.rn.bf16x2.f32 %0, %1, %2;" : "=r"(l) : "f"(r1), "f"(r0));
    hi = h; lo = l;
}

__device__ __forceinline__ float ex2(float x)
{
    float y;
    asm("ex2.approx.ftz.f32 %0, %1;" : "=f"(y) : "f"(x));
    return y;
}

__device__ __forceinline__ void cp16(uint32_t sa, const void* g)
{
    asm volatile("cp.async.cg.shared.global [%0], [%1], 16;"
                 :: "r"(sa), "l"(g) : "memory");
}
#define CP_COMMIT() asm volatile("cp.async.commit_group;" ::: "memory")
#define CP_WAIT(n)  asm volatile("cp.async.wait_group %0;" :: "n"(n) : "memory")

__device__ __forceinline__ void ldsm4(uint32_t r[4], uint32_t addr)
{
    asm volatile("ldmatrix.sync.aligned.m8n8.x4.shared.b16 {%0,%1,%2,%3}, [%4];"
                 : "=r"(r[0]), "=r"(r[1]), "=r"(r[2]), "=r"(r[3]) : "r"(addr));
}

// ---------------------------------------------------------------------------
// Kernel A: split + transpose W -> fused [192][384].  Also resets the
// persistent-qkv tile counter (stream-ordered before qkv).
// ---------------------------------------------------------------------------
__global__ __launch_bounds__(256) void splitw_kernel(const float* __restrict__ Wk,
                                                     const float* __restrict__ Wq,
                                                     const float* __restrict__ Wv)
{
    if (blockIdx.x == 0 && threadIdx.x == 0) g_qkv_ctr = 0;
    int c = blockIdx.x * 256 + threadIdx.x;     // 0 .. 36863
    int n = c & 63;
    int rest = c >> 6;
    int kp = rest % 192;
    int w = rest / 192;                          // 0=K, 1=Q, 2=V
    const float* W = (w == 0) ? Wk : (w == 1) ? Wq : Wv;
    float sc = (w == 1) ? 0.18033688011112042f : 1.0f;   // 0.125*log2(e)
    float v0 = W[(size_t)(2 * kp) * HH + n] * sc;
    float v1 = W[(size_t)(2 * kp + 1) * HH + n] * sc;
    uint32_t hi, lo;
    split2f(v0, v1, hi, lo);
    size_t o = ((size_t)w * 64 + n) * CC + 2 * kp;
    *(uint32_t*)&g_wthi[o] = hi;
    *(uint32_t*)&g_wtlo[o] = lo;
}

// ---------------------------------------------------------------------------
// Kernel B: fused QKV projection, cp.async double-buffered, ldmatrix frags.
// PERSISTENT: grid 296 (2/SM x 148), tiles claimed via atomic counter so
// per-SM work is balanced to within one tile (fixes the 512-CTA 3-vs-4
// sequential-CTA wave quantization, ~15% idle).
// ---------------------------------------------------------------------------
#define QKV_STG 40960
#define QKV_SMEM (2 * QKV_STG)
#define QX_H 0
#define QX_L 5120
#define QW_H 10240
#define QW_L 25600
#define QKV_TILES (BB * TT / 64)    // 512

__global__ __launch_bounds__(256, 2) void qkv_kernel(const float* __restrict__ x)
{
    extern __shared__ __align__(16) char qsm[];
    __shared__ int s_tile;
    const uint32_t sb = (uint32_t)__cvta_generic_to_shared(qsm);

    const int tid = threadIdx.x, w = tid >> 5, lane = tid & 31;
    const int g = lane >> 2, t = lane & 3;
    const int rg = (w & 3) * 16;
    const int cg = (w >> 2) * 96;

    const int arow = ((lane >> 3) & 1) * 8 + (lane & 7);
    const int acol = (lane >> 4) & 1;
    const int brow = ((lane >> 4) & 1) * 8 + (lane & 7);
    const int bcol = (lane >> 3) & 1;
    const uint32_t aoff = (uint32_t)((rg + arow) * 80 + acol * 16);
    const uint32_t boff = (uint32_t)((cg + brow) * 80 + bcol * 16);

    const int xr = tid >> 2, xc8 = (tid & 3) * 8;

    auto cpW = [&](int kb, int s) {
        uint32_t base = sb + s * QKV_STG;
#pragma unroll
        for (int it = 0; it < 3; it++) {
            int idx = tid + it * 256;
            int r = idx >> 2, c = idx & 3;
            cp16(base + QW_H + r * 80 + c * 16, g_wthi + (size_t)r * CC + kb * 32 + c * 8);
            cp16(base + QW_L + r * 80 + c * 16, g_wtlo + (size_t)r * CC + kb * 32 + c * 8);
        }
        CP_COMMIT();
    };
    auto stX = [&](int s, float4 v0, float4 v1) {
        uint32_t h01, l01, h23, l23, h45, l45, h67, l67;
        split2f(v0.x, v0.y, h01, l01);
        split2f(v0.z, v0.w, h23, l23);
        split2f(v1.x, v1.y, h45, l45);
        split2f(v1.z, v1.w, h67, l67);
        char* p = qsm + s * QKV_STG;
        *(uint4*)(p + QX_H + xr * 80 + xc8 * 2) = make_uint4(h01, h23, h45, h67);
        *(uint4*)(p + QX_L + xr * 80 + xc8 * 2) = make_uint4(l01, l23, l45, l67);
    };

    for (;;) {
        if (tid == 0) s_tile = atomicAdd(&g_qkv_ctr, 1);
        __syncthreads();
        const int tile = s_tile;
        __syncthreads();
        if (tile >= QKV_TILES) break;

        const int rowbase = tile * 64;
        const float* xrow = x + (size_t)(rowbase + xr) * CC + xc8;

        float acc[12][4];
#pragma unroll
        for (int i = 0; i < 12; i++)
#pragma unroll
            for (int j = 0; j < 4; j++) acc[i][j] = 0.0f;

        cpW(0, 0);
        float4 nv0 = *(const float4*)(xrow);
        float4 nv1 = *(const float4*)(xrow + 4);
        stX(0, nv0, nv1);
        nv0 = *(const float4*)(xrow + 32);
        nv1 = *(const float4*)(xrow + 36);

        for (int kb = 0; kb < 12; kb++) {
            const int s = kb & 1;
            __syncthreads();
            if (kb < 11) {
                stX(s ^ 1, nv0, nv1);
                cpW(kb + 1, s ^ 1);
                if (kb < 10) {
                    nv0 = *(const float4*)(xrow + (kb + 2) * 32);
                    nv1 = *(const float4*)(xrow + (kb + 2) * 32 + 4);
                }
                CP_WAIT(1);
            } else {
                CP_WAIT(0);
            }
            __syncthreads();

            const uint32_t st = sb + s * QKV_STG;
#pragma unroll
            for (int k2 = 0; k2 < 2; k2++) {
                uint32_t ah[4], al[4];
                ldsm4(ah, st + QX_H + aoff + k2 * 32);
                ldsm4(al, st + QX_L + aoff + k2 * 32);
#pragma unroll
                for (int p = 0; p < 6; p++) {
                    uint32_t bh4[4], bl4[4];
                    ldsm4(bh4, st + QW_H + boff + p * 1280 + k2 * 32);
                    ldsm4(bl4, st + QW_L + boff + p * 1280 + k2 * 32);
                    mma16816(acc[2 * p],     ah, bh4 + 0);
                    mma16816(acc[2 * p],     al, bh4 + 0);
                    mma16816(acc[2 * p],     ah, bl4 + 0);
                    mma16816(acc[2 * p + 1], ah, bh4 + 2);
                    mma16816(acc[2 * p + 1], al, bh4 + 2);
                    mma16816(acc[2 * p + 1], ah, bl4 + 2);
                }
            }
        }

        const int r0 = rowbase + rg + g;
        const int bidx = r0 >> 10;
        const int t0 = r0 & (TT - 1);
#pragma unroll
        for (int nt = 0; nt < 12; nt++) {
            int col = cg + nt * 8 + 2 * t;
            int m = col >> 6, cm = col & 63;
            if (m == 2) {
#pragma unroll
                for (int jj = 0; jj < 2; jj++) {
                    float v0 = acc[nt][jj];
                    float v1 = acc[nt][2 + jj];
                    size_t o = ((size_t)bidx * HH + cm + jj) * TT + t0;
                    bf16 h0 = __float2bfloat16(v0);
                    bf16 h1 = __float2bfloat16(v1);
                    g_vthi[o]     = h0;
                    g_vtlo[o]     = __float2bfloat16(v0 - __bfloat162float(h0));
                    g_vthi[o + 8] = h1;
                    g_vtlo[o + 8] = __float2bfloat16(v1 - __bfloat162float(h1));
                }
            } else {
                bf16* dh = (m == 1) ? g_qhi : g_khi;
                bf16* dl = (m == 1) ? g_qlo : g_klo;
                uint32_t h01, l01, h23, l23;
                split2f(acc[nt][0], acc[nt][1], h01, l01);
                split2f(acc[nt][2], acc[nt][3], h23, l23);
                *(uint32_t*)&dh[(size_t)r0 * HH + cm]       = h01;
                *(uint32_t*)&dl[(size_t)r0 * HH + cm]       = l01;
                *(uint32_t*)&dh[(size_t)(r0 + 8) * HH + cm] = h23;
                *(uint32_t*)&dl[(size_t)(r0 + 8) * HH + cm] = l23;
            }
        }
        __syncthreads();    // smem stages free before next tile's prologue
    }
}

// ---------------------------------------------------------------------------
// Kernel C: flash attention (R11-best config, verbatim).  64 queries/CTA,
// 4 warps, 4 CTAs/SM, 48KB smem.  K double-buffered, V single-buffered.
// Diagonal tile peeled + causal skip.  Epilogue interleaved with PV per
// key-chunk.  exp2 softmax (scale folded in Wq).
// ---------------------------------------------------------------------------
#define ATTN_SMEM 49152

__global__ __launch_bounds__(128, 4) void attn_kernel(float* __restrict__ out)
{
    extern __shared__ __align__(16) char asm_[];
    const uint32_t sbase = (uint32_t)__cvta_generic_to_shared(asm_);

    const int tid = threadIdx.x, w = tid >> 5, lane = tid & 31;
    const int g = lane >> 2, t = lane & 3;
    const int c = blockIdx.x;
    const int qt = 15 - (c >> 5);               // heavy tiles first globally
    const int b  = c & 31;
    const int qrow = qt * 64 + w * 16 + g;

    const int brow = ((lane >> 4) & 1) * 8 + (lane & 7);
    const int bcol = (lane >> 3) & 1;
    const int brm  = brow & 7;
    uint32_t xoff[4];
#pragma unroll
    for (int k2 = 0; k2 < 4; k2++)
        xoff[k2] = (uint32_t)(((k2 * 2 + bcol) ^ brm) << 4);
    const uint32_t rowb = (uint32_t)(brow * 128);

    const bf16* kbh = g_khi + (size_t)b * TT * HH;
    const bf16* kbl = g_klo + (size_t)b * TT * HH;
    const bf16* vbh = g_vthi + (size_t)b * HH * TT;
    const bf16* vbl = g_vtlo + (size_t)b * HH * TT;

    auto issueK = [&](int kt, int s) {
        const uint32_t st = sbase + s * 16384;
#pragma unroll
        for (int it = 0; it < 4; it++) {
            int idx = tid + it * 128;
            int r = idx >> 3, cc = idx & 7;
            uint32_t d = (uint32_t)(r * 128 + (((cc ^ (r & 7)) << 4)));
            cp16(st + d,        kbh + (size_t)kt * 4096 + idx * 8);
            cp16(st + 8192 + d, kbl + (size_t)kt * 4096 + idx * 8);
        }
        CP_COMMIT();
    };
    auto issueV = [&](int kt) {
        const uint32_t st = sbase + 32768;
#pragma unroll
        for (int it = 0; it < 4; it++) {
            int idx = tid + it * 128;
            int r = idx >> 3, cc = idx & 7;
            uint32_t d = (uint32_t)(r * 128 + (((cc ^ (r & 7)) << 4)));
            cp16(st + d,        vbh + (size_t)r * TT + kt * 64 + cc * 8);
            cp16(st + 8192 + d, vbl + (size_t)r * TT + kt * 64 + cc * 8);
        }
        CP_COMMIT();
    };

    issueK(0, 0);
    issueV(0);

    uint32_t qh[4][4], ql[4][4];
    {
        const bf16* qph = g_qhi + ((size_t)b * TT + qt * 64 + w * 16) * HH;
        const bf16* qpl = g_qlo + ((size_t)b * TT + qt * 64 + w * 16) * HH;
#pragma unroll
        for (int k2 = 0; k2 < 4; k2++) {
            int kc = k2 * 16 + 2 * t;
            qh[k2][0] = *(const uint32_t*)(qph + (size_t)g * HH + kc);
            qh[k2][1] = *(const uint32_t*)(qph + (size_t)(g + 8) * HH + kc);
            qh[k2][2] = *(const uint32_t*)(qph + (size_t)g * HH + kc + 8);
            qh[k2][3] = *(const uint32_t*)(qph + (size_t)(g + 8) * HH + kc + 8);
            ql[k2][0] = *(const uint32_t*)(qpl + (size_t)g * HH + kc);
            ql[k2][1] = *(const uint32_t*)(qpl + (size_t)(g + 8) * HH + kc);
            ql[k2][2] = *(const uint32_t*)(qpl + (size_t)g * HH + kc + 8);
            ql[k2][3] = *(const uint32_t*)(qpl + (size_t)(g + 8) * HH + kc + 8);
        }
    }

    float oacc[8][4];
#pragma unroll
    for (int i = 0; i < 8; i++)
#pragma unroll
        for (int j = 0; j < 4; j++) oacc[i][j] = 0.0f;
    float ls0 = 0.0f, ls1 = 0.0f;

    // Epilogue-for-one-chunk + PV-for-one-chunk, shared by both loop bodies.
    auto pv_chunk = [&](float sacc[8][4], int kv, int col0,
                        uint32_t stV, uint32_t stVl, bool mask) {
        uint32_t ph[4], pl[4];
#pragma unroll
        for (int j = 0; j < 2; j++) {
            int nt = 2 * kv + j;
            float e0, e1, e2, e3;
            if (mask) {
                int c0 = col0 + nt * 8;
                e0 = (c0     <= qrow)     ? ex2(sacc[nt][0]) : 0.0f;
                e1 = (c0 + 1 <= qrow)     ? ex2(sacc[nt][1]) : 0.0f;
                e2 = (c0     <= qrow + 8) ? ex2(sacc[nt][2]) : 0.0f;
                e3 = (c0 + 1 <= qrow + 8) ? ex2(sacc[nt][3]) : 0.0f;
            } else {
                e0 = ex2(sacc[nt][0]);
                e1 = ex2(sacc[nt][1]);
                e2 = ex2(sacc[nt][2]);
                e3 = ex2(sacc[nt][3]);
            }
            ls0 += e0 + e1;
            ls1 += e2 + e3;
            uint32_t h01, l01, h23, l23;
            split2f(e0, e1, h01, l01);
            split2f(e2, e3, h23, l23);
            ph[j * 2]     = h01;
            ph[j * 2 + 1] = h23;
            pl[j * 2]     = l01;
            pl[j * 2 + 1] = l23;
        }
#pragma unroll
        for (int p = 0; p < 4; p++) {
            uint32_t bh4[4], bl4[4];
            ldsm4(bh4, stV  + p * 2048 + xoff[kv]);
            ldsm4(bl4, stVl + p * 2048 + xoff[kv]);
            mma16816(oacc[2 * p],     ph, bh4 + 0);
            mma16816(oacc[2 * p],     pl, bh4 + 0);
            mma16816(oacc[2 * p],     ph, bl4 + 0);
            mma16816(oacc[2 * p + 1], ph, bh4 + 2);
            mma16816(oacc[2 * p + 1], pl, bh4 + 2);
            mma16816(oacc[2 * p + 1], ph, bl4 + 2);
        }
    };

    const uint32_t stVb  = sbase + 32768 + rowb;
    const uint32_t stVlb = stVb + 8192;

    // ---- Full (off-diagonal) tiles ----
    for (int kt = 0; kt < qt; kt++) {
        const int s = kt & 1;
        if (kt > 0) {
            __syncthreads();            // B1: PV(kt-1) reads done -> V free
            issueV(kt);
        }
        issueK(kt + 1, s ^ 1);
        CP_WAIT(2);                     // K(kt) landed
        __syncthreads();                // B2

        const uint32_t stK  = sbase + s * 16384 + rowb;
        const uint32_t stKl = stK + 8192;

        float sacc[8][4];
#pragma unroll
        for (int i = 0; i < 8; i++)
#pragma unroll
            for (int j = 0; j < 4; j++) sacc[i][j] = 0.0f;
#pragma unroll
        for (int k2 = 0; k2 < 4; k2++) {
#pragma unroll
            for (int p = 0; p < 4; p++) {
                uint32_t bh4[4], bl4[4];
                ldsm4(bh4, stK  + p * 2048 + xoff[k2]);
                ldsm4(bl4, stKl + p * 2048 + xoff[k2]);
                mma16816(sacc[2 * p],     qh[k2], bh4 + 0);
                mma16816(sacc[2 * p],     ql[k2], bh4 + 0);
                mma16816(sacc[2 * p],     qh[k2], bl4 + 0);
                mma16816(sacc[2 * p + 1], qh[k2], bh4 + 2);
                mma16816(sacc[2 * p + 1], ql[k2], bh4 + 2);
                mma16816(sacc[2 * p + 1], qh[k2], bl4 + 2);
            }
        }

        CP_WAIT(1);                     // V(kt) landed (K(kt+1) in flight)
        __syncthreads();                // B3

#pragma unroll
        for (int kv = 0; kv < 4; kv++)
            pv_chunk(sacc, kv, 0, stVb, stVlb, false);
    }

    // ---- Diagonal tile (kt == qt), causal-skipped ----
    {
        const int s = qt & 1;
        if (qt > 0) {
            __syncthreads();
            issueV(qt);
        }
        CP_WAIT(1);                     // K(qt) landed
        __syncthreads();

        const uint32_t stK  = sbase + s * 16384 + rowb;
        const uint32_t stKl = stK + 8192;
        const int pmax = w + 1;

        float sacc[8][4];
#pragma unroll
        for (int i = 0; i < 8; i++)
#pragma unroll
            for (int j = 0; j < 4; j++) sacc[i][j] = 0.0f;
#pragma unroll
        for (int k2 = 0; k2 < 4; k2++) {
            for (int p = 0; p < pmax; p++) {
                uint32_t bh4[4], bl4[4];
                ldsm4(bh4, stK  + p * 2048 + xoff[k2]);
                ldsm4(bl4, stKl + p * 2048 + xoff[k2]);
                mma16816(sacc[2 * p],     qh[k2], bh4 + 0);
                mma16816(sacc[2 * p],     ql[k2], bh4 + 0);
                mma16816(sacc[2 * p],     qh[k2], bl4 + 0);
                mma16816(sacc[2 * p + 1], qh[k2], bh4 + 2);
                mma16816(sacc[2 * p + 1], ql[k2], bh4 + 2);
                mma16816(sacc[2 * p + 1], qh[k2], bl4 + 2);
            }
        }

        CP_WAIT(0);                     // V(qt) landed
        __syncthreads();

        const int col0 = qt * 64 + 2 * t;
        for (int kv = 0; kv < pmax; kv++)
            pv_chunk(sacc, kv, col0, stVb, stVlb, true);
    }

    ls0 += __shfl_xor_sync(0xffffffffu, ls0, 1);
    ls0 += __shfl_xor_sync(0xffffffffu, ls0, 2);
    ls1 += __shfl_xor_sync(0xffffffffu, ls1, 1);
    ls1 += __shfl_xor_sync(0xffffffffu, ls1, 2);
    float i0 = 1.0f / ls0, i1 = 1.0f / ls1;

    float* op = out + ((size_t)b * TT + qrow) * HH;
#pragma unroll
    for (int nt = 0; nt < 8; nt++) {
        int col = nt * 8 + 2 * t;
        *(float2*)(op + col)          = make_float2(oacc[nt][0] * i0, oacc[nt][1] * i0);
        *(float2*)(op + 8 * HH + col) = make_float2(oacc[nt][2] * i1, oacc[nt][3] * i1);
    }
}

// ---------------------------------------------------------------------------
extern "C" void kernel_launch(void* const* d_in, const int* in_sizes, int n_in,
                              void* d_out, int out_size)
{
    const float* x  = (const float*)d_in[0];
    const float* Wk = (const float*)d_in[1];
    const float* Wq = (const float*)d_in[2];
    const float* Wv = (const float*)d_in[3];
    float* out = (float*)d_out;
    (void)in_sizes; (void)n_in; (void)out_size;

    splitw_kernel<<<144, 256>>>(Wk, Wq, Wv);

    cudaFuncSetAttribute(qkv_kernel,
                         cudaFuncAttributeMaxDynamicSharedMemorySize,
                         QKV_SMEM);
    qkv_kernel<<<296, 256, QKV_SMEM>>>(x);

    cudaFuncSetAttribute(attn_kernel,
                         cudaFuncAttributeMaxDynamicSharedMemorySize,
                         ATTN_SMEM);
    attn_kernel<<<512, 128, ATTN_SMEM>>>(out);
}

// round 16
// speedup vs baseline: 1.3634x; 1.2928x over previous
#include <cuda_runtime.h>
#include <cuda_bf16.h>
#include <cuda_fp16.h>
#include <stdint.h>

#define BB 32
#define TT 1024
#define CC 384
#define HH 64

// fp16 full*split scheme: A operands (x, q, P) rounded to single fp16;
// B operands (W, k, v) split into fp16 hi+lo (exact to ~22 bits).
// Weights fused [n=192][k=384]; Wq pre-scaled by 0.125*log2(e) (exp2 softmax).
__device__ __half g_wthi[192*CC], g_wtlo[192*CC];
__device__ __half g_qf [BB*TT*HH];                       // q rounded fp16
__device__ __half g_khi[BB*TT*HH], g_klo[BB*TT*HH];
__device__ __half g_vthi[BB*HH*TT], g_vtlo[BB*HH*TT];    // [b][h][t]

// ---------------------------------------------------------------------------
__device__ __forceinline__ void mmah(float d[4], const uint32_t a[4],
                                     const uint32_t b[2])
{
    asm volatile(
        "mma.sync.aligned.m16n8k16.row.col.f32.f16.f16.f32 "
        "{%0,%1,%2,%3}, {%4,%5,%6,%7}, {%8,%9}, {%0,%1,%2,%3};"
        : "+f"(d[0]), "+f"(d[1]), "+f"(d[2]), "+f"(d[3])
        : "r"(a[0]), "r"(a[1]), "r"(a[2]), "r"(a[3]), "r"(b[0]), "r"(b[1]));
}

// Pack (v0, v1) -> f16x2 word, v0 in low half.
__device__ __forceinline__ uint32_t pack2h(float v0, float v1)
{
    uint32_t h;
    asm("cvt.rn.f16x2.f32 %0, %1, %2;" : "=r"(h) : "f"(v1), "f"(v0));
    return h;
}

// Split (v0, v1) -> f16x2 hi + f16x2 lo (residual).
__device__ __forceinline__ void split2h(float v0, float v1,
                                        uint32_t& hi, uint32_t& lo)
{
    uint32_t h = pack2h(v0, v1);
    float h0f, h1f;
    asm("{ .reg .f16 l, u; mov.b32 {l, u}, %2; cvt.f32.f16 %0, l; cvt.f32.f16 %1, u; }"
        : "=f"(h0f), "=f"(h1f) : "r"(h));
    hi = h;
    lo = pack2h(v0 - h0f, v1 - h1f);
}

__device__ __forceinline__ float ex2(float x)
{
    float y;
    asm("ex2.approx.ftz.f32 %0, %1;" : "=f"(y) : "f"(x));
    return y;
}

__device__ __forceinline__ void cp16(uint32_t sa, const void* g)
{
    asm volatile("cp.async.cg.shared.global [%0], [%1], 16;"
                 :: "r"(sa), "l"(g) : "memory");
}
#define CP_COMMIT() asm volatile("cp.async.commit_group;" ::: "memory")
#define CP_WAIT(n)  asm volatile("cp.async.wait_group %0;" :: "n"(n) : "memory")

__device__ __forceinline__ void ldsm4(uint32_t r[4], uint32_t addr)
{
    asm volatile("ldmatrix.sync.aligned.m8n8.x4.shared.b16 {%0,%1,%2,%3}, [%4];"
                 : "=r"(r[0]), "=r"(r[1]), "=r"(r[2]), "=r"(r[3]) : "r"(addr));
}

// ---------------------------------------------------------------------------
// Kernel A: split + transpose W -> fused fp16 hi/lo [192][384].
// ---------------------------------------------------------------------------
__global__ __launch_bounds__(256) void splitw_kernel(const float* __restrict__ Wk,
                                                     const float* __restrict__ Wq,
                                                     const float* __restrict__ Wv)
{
    int c = blockIdx.x * 256 + threadIdx.x;     // 0 .. 36863
    int n = c & 63;
    int rest = c >> 6;
    int kp = rest % 192;
    int w = rest / 192;                          // 0=K, 1=Q, 2=V
    const float* W = (w == 0) ? Wk : (w == 1) ? Wq : Wv;
    float sc = (w == 1) ? 0.18033688011112042f : 1.0f;   // 0.125*log2(e)
    float v0 = W[(size_t)(2 * kp) * HH + n] * sc;
    float v1 = W[(size_t)(2 * kp + 1) * HH + n] * sc;
    uint32_t hi, lo;
    split2h(v0, v1, hi, lo);
    size_t o = ((size_t)w * 64 + n) * CC + 2 * kp;
    *(uint32_t*)&g_wthi[o] = hi;
    *(uint32_t*)&g_wtlo[o] = lo;
}

// ---------------------------------------------------------------------------
// Kernel B: fused QKV projection (fp16 full*split 2-pass).
// x rounded to fp16 in smem (single array); W fp16 hi/lo via cp.async.
// Stage layout (bytes, pitch 80 = 16-aligned): XF 0 (64x80), WH 5120
// (192x80), WL 20480.  Stage 35840 x 2 = 71680 bytes.
// ---------------------------------------------------------------------------
#define QKV_STG 35840
#define QKV_SMEM (2 * QKV_STG)
#define QX_F 0
#define QW_H 5120
#define QW_L 20480

__global__ __launch_bounds__(256, 2) void qkv_kernel(const float* __restrict__ x)
{
    extern __shared__ __align__(16) char qsm[];
    const uint32_t sb = (uint32_t)__cvta_generic_to_shared(qsm);

    const int tid = threadIdx.x, w = tid >> 5, lane = tid & 31;
    const int g = lane >> 2, t = lane & 3;
    const int rowbase = blockIdx.x * 64;
    const int rg = (w & 3) * 16;
    const int cg = (w >> 2) * 96;

    const int arow = ((lane >> 3) & 1) * 8 + (lane & 7);
    const int acol = (lane >> 4) & 1;
    const int brow = ((lane >> 4) & 1) * 8 + (lane & 7);
    const int bcol = (lane >> 3) & 1;
    const uint32_t aoff = (uint32_t)((rg + arow) * 80 + acol * 16);
    const uint32_t boff = (uint32_t)((cg + brow) * 80 + bcol * 16);

    const int xr = tid >> 2, xc8 = (tid & 3) * 8;
    const float* xrow = x + (size_t)(rowbase + xr) * CC + xc8;

    auto cpW = [&](int kb, int s) {
        uint32_t base = sb + s * QKV_STG;
#pragma unroll
        for (int it = 0; it < 3; it++) {
            int idx = tid + it * 256;
            int r = idx >> 2, c = idx & 3;
            cp16(base + QW_H + r * 80 + c * 16, g_wthi + (size_t)r * CC + kb * 32 + c * 8);
            cp16(base + QW_L + r * 80 + c * 16, g_wtlo + (size_t)r * CC + kb * 32 + c * 8);
        }
        CP_COMMIT();
    };
    auto stX = [&](int s, float4 v0, float4 v1) {
        uint32_t p0 = pack2h(v0.x, v0.y);
        uint32_t p1 = pack2h(v0.z, v0.w);
        uint32_t p2 = pack2h(v1.x, v1.y);
        uint32_t p3 = pack2h(v1.z, v1.w);
        char* p = qsm + s * QKV_STG;
        *(uint4*)(p + QX_F + xr * 80 + xc8 * 2) = make_uint4(p0, p1, p2, p3);
    };

    float acc[12][4];
#pragma unroll
    for (int i = 0; i < 12; i++)
#pragma unroll
        for (int j = 0; j < 4; j++) acc[i][j] = 0.0f;

    cpW(0, 0);
    float4 nv0 = *(const float4*)(xrow);
    float4 nv1 = *(const float4*)(xrow + 4);
    stX(0, nv0, nv1);
    nv0 = *(const float4*)(xrow + 32);
    nv1 = *(const float4*)(xrow + 36);

    for (int kb = 0; kb < 12; kb++) {
        const int s = kb & 1;
        __syncthreads();
        if (kb < 11) {
            stX(s ^ 1, nv0, nv1);
            cpW(kb + 1, s ^ 1);
            if (kb < 10) {
                nv0 = *(const float4*)(xrow + (kb + 2) * 32);
                nv1 = *(const float4*)(xrow + (kb + 2) * 32 + 4);
            }
            CP_WAIT(1);
        } else {
            CP_WAIT(0);
        }
        __syncthreads();

        const uint32_t st = sb + s * QKV_STG;
#pragma unroll
        for (int k2 = 0; k2 < 2; k2++) {
            uint32_t af[4];
            ldsm4(af, st + QX_F + aoff + k2 * 32);
#pragma unroll
            for (int p = 0; p < 6; p++) {
                uint32_t bh4[4], bl4[4];
                ldsm4(bh4, st + QW_H + boff + p * 1280 + k2 * 32);
                ldsm4(bl4, st + QW_L + boff + p * 1280 + k2 * 32);
                mmah(acc[2 * p],     af, bh4 + 0);
                mmah(acc[2 * p],     af, bl4 + 0);
                mmah(acc[2 * p + 1], af, bh4 + 2);
                mmah(acc[2 * p + 1], af, bl4 + 2);
            }
        }
    }

    // Epilogue: q -> fp16 rounded; k -> fp16 hi/lo; v -> transposed fp16 hi/lo.
    const int r0 = rowbase + rg + g;
    const int bidx = r0 >> 10;
    const int t0 = r0 & (TT - 1);
#pragma unroll
    for (int nt = 0; nt < 12; nt++) {
        int col = cg + nt * 8 + 2 * t;
        int m = col >> 6, cm = col & 63;
        if (m == 2) {
#pragma unroll
            for (int jj = 0; jj < 2; jj++) {
                float v0 = acc[nt][jj];        // row r0
                float v1 = acc[nt][2 + jj];    // row r0+8
                size_t o = ((size_t)bidx * HH + cm + jj) * TT + t0;
                __half h0 = __float2half(v0);
                __half h1 = __float2half(v1);
                g_vthi[o]     = h0;
                g_vtlo[o]     = __float2half(v0 - __half2float(h0));
                g_vthi[o + 8] = h1;
                g_vtlo[o + 8] = __float2half(v1 - __half2float(h1));
            }
        } else if (m == 1) {
            *(uint32_t*)&g_qf[(size_t)r0 * HH + cm]       = pack2h(acc[nt][0], acc[nt][1]);
            *(uint32_t*)&g_qf[(size_t)(r0 + 8) * HH + cm] = pack2h(acc[nt][2], acc[nt][3]);
        } else {
            uint32_t h01, l01, h23, l23;
            split2h(acc[nt][0], acc[nt][1], h01, l01);
            split2h(acc[nt][2], acc[nt][3], h23, l23);
            *(uint32_t*)&g_khi[(size_t)r0 * HH + cm]       = h01;
            *(uint32_t*)&g_klo[(size_t)r0 * HH + cm]       = l01;
            *(uint32_t*)&g_khi[(size_t)(r0 + 8) * HH + cm] = h23;
            *(uint32_t*)&g_klo[(size_t)(r0 + 8) * HH + cm] = l23;
        }
    }
}

// ---------------------------------------------------------------------------
// Kernel C: flash attention (R11 structure, fp16 full*split 2-pass).
// 64 queries/CTA, 4 warps, 4 CTAs/SM, 48KB smem.  K double-buffered,
// V single-buffered.  Diagonal tile peeled + causal skip.  Epilogue
// interleaved with PV per key-chunk; P packed fp16 in 1 cvt/pair.
// ---------------------------------------------------------------------------
#define ATTN_SMEM 49152

__global__ __launch_bounds__(128, 4) void attn_kernel(float* __restrict__ out)
{
    extern __shared__ __align__(16) char asm_[];
    const uint32_t sbase = (uint32_t)__cvta_generic_to_shared(asm_);

    const int tid = threadIdx.x, w = tid >> 5, lane = tid & 31;
    const int g = lane >> 2, t = lane & 3;
    const int c = blockIdx.x;
    const int qt = 15 - (c >> 5);               // heavy tiles first globally
    const int b  = c & 31;
    const int qrow = qt * 64 + w * 16 + g;

    const int brow = ((lane >> 4) & 1) * 8 + (lane & 7);
    const int bcol = (lane >> 3) & 1;
    const int brm  = brow & 7;
    uint32_t xoff[4];
#pragma unroll
    for (int k2 = 0; k2 < 4; k2++)
        xoff[k2] = (uint32_t)(((k2 * 2 + bcol) ^ brm) << 4);
    const uint32_t rowb = (uint32_t)(brow * 128);

    const __half* kbh = g_khi + (size_t)b * TT * HH;
    const __half* kbl = g_klo + (size_t)b * TT * HH;
    const __half* vbh = g_vthi + (size_t)b * HH * TT;
    const __half* vbl = g_vtlo + (size_t)b * HH * TT;

    auto issueK = [&](int kt, int s) {
        const uint32_t st = sbase + s * 16384;
#pragma unroll
        for (int it = 0; it < 4; it++) {
            int idx = tid + it * 128;
            int r = idx >> 3, cc = idx & 7;
            uint32_t d = (uint32_t)(r * 128 + (((cc ^ (r & 7)) << 4)));
            cp16(st + d,        kbh + (size_t)kt * 4096 + idx * 8);
            cp16(st + 8192 + d, kbl + (size_t)kt * 4096 + idx * 8);
        }
        CP_COMMIT();
    };
    auto issueV = [&](int kt) {
        const uint32_t st = sbase + 32768;
#pragma unroll
        for (int it = 0; it < 4; it++) {
            int idx = tid + it * 128;
            int r = idx >> 3, cc = idx & 7;
            uint32_t d = (uint32_t)(r * 128 + (((cc ^ (r & 7)) << 4)));
            cp16(st + d,        vbh + (size_t)r * TT + kt * 64 + cc * 8);
            cp16(st + 8192 + d, vbl + (size_t)r * TT + kt * 64 + cc * 8);
        }
        CP_COMMIT();
    };

    issueK(0, 0);
    issueV(0);

    // Persistent Q fragments (single fp16 set — half the registers of hi/lo).
    uint32_t qf[4][4];
    {
        const __half* qp = g_qf + ((size_t)b * TT + qt * 64 + w * 16) * HH;
#pragma unroll
        for (int k2 = 0; k2 < 4; k2++) {
            int kc = k2 * 16 + 2 * t;
            qf[k2][0] = *(const uint32_t*)(qp + (size_t)g * HH + kc);
            qf[k2][1] = *(const uint32_t*)(qp + (size_t)(g + 8) * HH + kc);
            qf[k2][2] = *(const uint32_t*)(qp + (size_t)g * HH + kc + 8);
            qf[k2][3] = *(const uint32_t*)(qp + (size_t)(g + 8) * HH + kc + 8);
        }
    }

    float oacc[8][4];
#pragma unroll
    for (int i = 0; i < 8; i++)
#pragma unroll
        for (int j = 0; j < 4; j++) oacc[i][j] = 0.0f;
    float ls0 = 0.0f, ls1 = 0.0f;

    // Epilogue-for-one-chunk + PV-for-one-chunk.
    auto pv_chunk = [&](float sacc[8][4], int kv, int col0,
                        uint32_t stV, uint32_t stVl, bool mask) {
        uint32_t pf[4];
#pragma unroll
        for (int j = 0; j < 2; j++) {
            int nt = 2 * kv + j;
            float e0, e1, e2, e3;
            if (mask) {
                int c0 = col0 + nt * 8;
                e0 = (c0     <= qrow)     ? ex2(sacc[nt][0]) : 0.0f;
                e1 = (c0 + 1 <= qrow)     ? ex2(sacc[nt][1]) : 0.0f;
                e2 = (c0     <= qrow + 8) ? ex2(sacc[nt][2]) : 0.0f;
                e3 = (c0 + 1 <= qrow + 8) ? ex2(sacc[nt][3]) : 0.0f;
            } else {
                e0 = ex2(sacc[nt][0]);
                e1 = ex2(sacc[nt][1]);
                e2 = ex2(sacc[nt][2]);
                e3 = ex2(sacc[nt][3]);
            }
            ls0 += e0 + e1;
            ls1 += e2 + e3;
            pf[j * 2]     = pack2h(e0, e1);   // row g,   k-half j
            pf[j * 2 + 1] = pack2h(e2, e3);   // row g+8, k-half j
        }
#pragma unroll
        for (int p = 0; p < 4; p++) {
            uint32_t bh4[4], bl4[4];
            ldsm4(bh4, stV  + p * 2048 + xoff[kv]);
            ldsm4(bl4, stVl + p * 2048 + xoff[kv]);
            mmah(oacc[2 * p],     pf, bh4 + 0);
            mmah(oacc[2 * p],     pf, bl4 + 0);
            mmah(oacc[2 * p + 1], pf, bh4 + 2);
            mmah(oacc[2 * p + 1], pf, bl4 + 2);
        }
    };

    const uint32_t stVb  = sbase + 32768 + rowb;
    const uint32_t stVlb = stVb + 8192;

    // ---- Full (off-diagonal) tiles ----
    for (int kt = 0; kt < qt; kt++) {
        const int s = kt & 1;
        if (kt > 0) {
            __syncthreads();            // B1: PV(kt-1) reads done -> V free
            issueV(kt);
        }
        issueK(kt + 1, s ^ 1);
        CP_WAIT(2);                     // K(kt) landed
        __syncthreads();                // B2

        const uint32_t stK  = sbase + s * 16384 + rowb;
        const uint32_t stKl = stK + 8192;

        float sacc[8][4];
#pragma unroll
        for (int i = 0; i < 8; i++)
#pragma unroll
            for (int j = 0; j < 4; j++) sacc[i][j] = 0.0f;
#pragma unroll
        for (int k2 = 0; k2 < 4; k2++) {
#pragma unroll
            for (int p = 0; p < 4; p++) {
                uint32_t bh4[4], bl4[4];
                ldsm4(bh4, stK  + p * 2048 + xoff[k2]);
                ldsm4(bl4, stKl + p * 2048 + xoff[k2]);
                mmah(sacc[2 * p],     qf[k2], bh4 + 0);
                mmah(sacc[2 * p],     qf[k2], bl4 + 0);
                mmah(sacc[2 * p + 1], qf[k2], bh4 + 2);
                mmah(sacc[2 * p + 1], qf[k2], bl4 + 2);
            }
        }

        CP_WAIT(1);                     // V(kt) landed (K(kt+1) in flight)
        __syncthreads();                // B3

#pragma unroll
        for (int kv = 0; kv < 4; kv++)
            pv_chunk(sacc, kv, 0, stVb, stVlb, false);
    }

    // ---- Diagonal tile (kt == qt), causal-skipped ----
    {
        const int s = qt & 1;
        if (qt > 0) {
            __syncthreads();
            issueV(qt);
        }
        CP_WAIT(1);                     // K(qt) landed
        __syncthreads();

        const uint32_t stK  = sbase + s * 16384 + rowb;
        const uint32_t stKl = stK + 8192;
        const int pmax = w + 1;

        float sacc[8][4];
#pragma unroll
        for (int i = 0; i < 8; i++)
#pragma unroll
            for (int j = 0; j < 4; j++) sacc[i][j] = 0.0f;
#pragma unroll
        for (int k2 = 0; k2 < 4; k2++) {
            for (int p = 0; p < pmax; p++) {
                uint32_t bh4[4], bl4[4];
                ldsm4(bh4, stK  + p * 2048 + xoff[k2]);
                ldsm4(bl4, stKl + p * 2048 + xoff[k2]);
                mmah(sacc[2 * p],     qf[k2], bh4 + 0);
                mmah(sacc[2 * p],     qf[k2], bl4 + 0);
                mmah(sacc[2 * p + 1], qf[k2], bh4 + 2);
                mmah(sacc[2 * p + 1], qf[k2], bl4 + 2);
            }
        }

        CP_WAIT(0);                     // V(qt) landed
        __syncthreads();

        const int col0 = qt * 64 + 2 * t;
        for (int kv = 0; kv < pmax; kv++)
            pv_chunk(sacc, kv, col0, stVb, stVlb, true);
    }

    ls0 += __shfl_xor_sync(0xffffffffu, ls0, 1);
    ls0 += __shfl_xor_sync(0xffffffffu, ls0, 2);
    ls1 += __shfl_xor_sync(0xffffffffu, ls1, 1);
    ls1 += __shfl_xor_sync(0xffffffffu, ls1, 2);
    float i0 = 1.0f / ls0, i1 = 1.0f / ls1;

    float* op = out + ((size_t)b * TT + qrow) * HH;
#pragma unroll
    for (int nt = 0; nt < 8; nt++) {
        int col = nt * 8 + 2 * t;
        *(float2*)(op + col)          = make_float2(oacc[nt][0] * i0, oacc[nt][1] * i0);
        *(float2*)(op + 8 * HH + col) = make_float2(oacc[nt][2] * i1, oacc[nt][3] * i1);
    }
}

// ---------------------------------------------------------------------------
extern "C" void kernel_launch(void* const* d_in, const int* in_sizes, int n_in,
                              void* d_out, int out_size)
{
    const float* x  = (const float*)d_in[0];
    const float* Wk = (const float*)d_in[1];
    const float* Wq = (const float*)d_in[2];
    const float* Wv = (const float*)d_in[3];
    float* out = (float*)d_out;
    (void)in_sizes; (void)n_in; (void)out_size;

    splitw_kernel<<<144, 256>>>(Wk, Wq, Wv);

    cudaFuncSetAttribute(qkv_kernel,
                         cudaFuncAttributeMaxDynamicSharedMemorySize,
                         QKV_SMEM);
    qkv_kernel<<<BB * TT / 64, 256, QKV_SMEM>>>(x);

    cudaFuncSetAttribute(attn_kernel,
                         cudaFuncAttributeMaxDynamicSharedMemorySize,
                         ATTN_SMEM);
    attn_kernel<<<512, 128, ATTN_SMEM>>>(out);
}

// round 17
// speedup vs baseline: 1.6263x; 1.1928x over previous
#include <cuda_runtime.h>
#include <cuda_bf16.h>
#include <cuda_fp16.h>
#include <stdint.h>

#define BB 32
#define TT 1024
#define CC 384
#define HH 64

// fp16 scheme: W split hi/lo (2-pass qkv); q,k,v,P single-rounded fp16
// (pure-fp16 attention — calibrated error model: 6 stages x 2^-12 ~ 5.9e-4).
// Weights fused [n=192][k=384]; Wq pre-scaled by 0.125*log2(e) (exp2 softmax).
__device__ __half g_wthi[192*CC], g_wtlo[192*CC];
__device__ __half g_qf[BB*TT*HH];
__device__ __half g_kf[BB*TT*HH];
__device__ __half g_vtf[BB*HH*TT];                       // [b][h][t]

// ---------------------------------------------------------------------------
__device__ __forceinline__ void mmah(float d[4], const uint32_t a[4],
                                     const uint32_t b[2])
{
    asm volatile(
        "mma.sync.aligned.m16n8k16.row.col.f32.f16.f16.f32 "
        "{%0,%1,%2,%3}, {%4,%5,%6,%7}, {%8,%9}, {%0,%1,%2,%3};"
        : "+f"(d[0]), "+f"(d[1]), "+f"(d[2]), "+f"(d[3])
        : "r"(a[0]), "r"(a[1]), "r"(a[2]), "r"(a[3]), "r"(b[0]), "r"(b[1]));
}

__device__ __forceinline__ uint32_t pack2h(float v0, float v1)
{
    uint32_t h;
    asm("cvt.rn.f16x2.f32 %0, %1, %2;" : "=r"(h) : "f"(v1), "f"(v0));
    return h;
}

__device__ __forceinline__ void split2h(float v0, float v1,
                                        uint32_t& hi, uint32_t& lo)
{
    uint32_t h = pack2h(v0, v1);
    float h0f, h1f;
    asm("{ .reg .f16 l, u; mov.b32 {l, u}, %2; cvt.f32.f16 %0, l; cvt.f32.f16 %1, u; }"
        : "=f"(h0f), "=f"(h1f) : "r"(h));
    hi = h;
    lo = pack2h(v0 - h0f, v1 - h1f);
}

__device__ __forceinline__ float ex2(float x)
{
    float y;
    asm("ex2.approx.ftz.f32 %0, %1;" : "=f"(y) : "f"(x));
    return y;
}

__device__ __forceinline__ void cp16(uint32_t sa, const void* g)
{
    asm volatile("cp.async.cg.shared.global [%0], [%1], 16;"
                 :: "r"(sa), "l"(g) : "memory");
}
#define CP_COMMIT() asm volatile("cp.async.commit_group;" ::: "memory")
#define CP_WAIT(n)  asm volatile("cp.async.wait_group %0;" :: "n"(n) : "memory")

__device__ __forceinline__ void ldsm4(uint32_t r[4], uint32_t addr)
{
    asm volatile("ldmatrix.sync.aligned.m8n8.x4.shared.b16 {%0,%1,%2,%3}, [%4];"
                 : "=r"(r[0]), "=r"(r[1]), "=r"(r[2]), "=r"(r[3]) : "r"(addr));
}

// ---------------------------------------------------------------------------
// Kernel A: split + transpose W -> fused fp16 hi/lo [192][384].
// ---------------------------------------------------------------------------
__global__ __launch_bounds__(256) void splitw_kernel(const float* __restrict__ Wk,
                                                     const float* __restrict__ Wq,
                                                     const float* __restrict__ Wv)
{
    int c = blockIdx.x * 256 + threadIdx.x;     // 0 .. 36863
    int n = c & 63;
    int rest = c >> 6;
    int kp = rest % 192;
    int w = rest / 192;                          // 0=K, 1=Q, 2=V
    const float* W = (w == 0) ? Wk : (w == 1) ? Wq : Wv;
    float sc = (w == 1) ? 0.18033688011112042f : 1.0f;   // 0.125*log2(e)
    float v0 = W[(size_t)(2 * kp) * HH + n] * sc;
    float v1 = W[(size_t)(2 * kp + 1) * HH + n] * sc;
    uint32_t hi, lo;
    split2h(v0, v1, hi, lo);
    size_t o = ((size_t)w * 64 + n) * CC + 2 * kp;
    *(uint32_t*)&g_wthi[o] = hi;
    *(uint32_t*)&g_wtlo[o] = lo;
}

// ---------------------------------------------------------------------------
// Kernel B: fused QKV projection (fp16 full*split 2-pass), as R16.
// Stage layout (bytes, pitch 80): XF 0 (64x80), WH 5120 (192x80), WL 20480.
// ---------------------------------------------------------------------------
#define QKV_STG 35840
#define QKV_SMEM (2 * QKV_STG)
#define QX_F 0
#define QW_H 5120
#define QW_L 20480

__global__ __launch_bounds__(256, 2) void qkv_kernel(const float* __restrict__ x)
{
    extern __shared__ __align__(16) char qsm[];
    const uint32_t sb = (uint32_t)__cvta_generic_to_shared(qsm);

    const int tid = threadIdx.x, w = tid >> 5, lane = tid & 31;
    const int g = lane >> 2, t = lane & 3;
    const int rowbase = blockIdx.x * 64;
    const int rg = (w & 3) * 16;
    const int cg = (w >> 2) * 96;

    const int arow = ((lane >> 3) & 1) * 8 + (lane & 7);
    const int acol = (lane >> 4) & 1;
    const int brow = ((lane >> 4) & 1) * 8 + (lane & 7);
    const int bcol = (lane >> 3) & 1;
    const uint32_t aoff = (uint32_t)((rg + arow) * 80 + acol * 16);
    const uint32_t boff = (uint32_t)((cg + brow) * 80 + bcol * 16);

    const int xr = tid >> 2, xc8 = (tid & 3) * 8;
    const float* xrow = x + (size_t)(rowbase + xr) * CC + xc8;

    auto cpW = [&](int kb, int s) {
        uint32_t base = sb + s * QKV_STG;
#pragma unroll
        for (int it = 0; it < 3; it++) {
            int idx = tid + it * 256;
            int r = idx >> 2, c = idx & 3;
            cp16(base + QW_H + r * 80 + c * 16, g_wthi + (size_t)r * CC + kb * 32 + c * 8);
            cp16(base + QW_L + r * 80 + c * 16, g_wtlo + (size_t)r * CC + kb * 32 + c * 8);
        }
        CP_COMMIT();
    };
    auto stX = [&](int s, float4 v0, float4 v1) {
        uint32_t p0 = pack2h(v0.x, v0.y);
        uint32_t p1 = pack2h(v0.z, v0.w);
        uint32_t p2 = pack2h(v1.x, v1.y);
        uint32_t p3 = pack2h(v1.z, v1.w);
        char* p = qsm + s * QKV_STG;
        *(uint4*)(p + QX_F + xr * 80 + xc8 * 2) = make_uint4(p0, p1, p2, p3);
    };

    float acc[12][4];
#pragma unroll
    for (int i = 0; i < 12; i++)
#pragma unroll
        for (int j = 0; j < 4; j++) acc[i][j] = 0.0f;

    cpW(0, 0);
    float4 nv0 = *(const float4*)(xrow);
    float4 nv1 = *(const float4*)(xrow + 4);
    stX(0, nv0, nv1);
    nv0 = *(const float4*)(xrow + 32);
    nv1 = *(const float4*)(xrow + 36);

    for (int kb = 0; kb < 12; kb++) {
        const int s = kb & 1;
        __syncthreads();
        if (kb < 11) {
            stX(s ^ 1, nv0, nv1);
            cpW(kb + 1, s ^ 1);
            if (kb < 10) {
                nv0 = *(const float4*)(xrow + (kb + 2) * 32);
                nv1 = *(const float4*)(xrow + (kb + 2) * 32 + 4);
            }
            CP_WAIT(1);
        } else {
            CP_WAIT(0);
        }
        __syncthreads();

        const uint32_t st = sb + s * QKV_STG;
#pragma unroll
        for (int k2 = 0; k2 < 2; k2++) {
            uint32_t af[4];
            ldsm4(af, st + QX_F + aoff + k2 * 32);
#pragma unroll
            for (int p = 0; p < 6; p++) {
                uint32_t bh4[4], bl4[4];
                ldsm4(bh4, st + QW_H + boff + p * 1280 + k2 * 32);
                ldsm4(bl4, st + QW_L + boff + p * 1280 + k2 * 32);
                mmah(acc[2 * p],     af, bh4 + 0);
                mmah(acc[2 * p],     af, bl4 + 0);
                mmah(acc[2 * p + 1], af, bh4 + 2);
                mmah(acc[2 * p + 1], af, bl4 + 2);
            }
        }
    }

    // Epilogue: q, k -> fp16 rounded; v -> transposed fp16 rounded.
    const int r0 = rowbase + rg + g;
    const int bidx = r0 >> 10;
    const int t0 = r0 & (TT - 1);
#pragma unroll
    for (int nt = 0; nt < 12; nt++) {
        int col = cg + nt * 8 + 2 * t;
        int m = col >> 6, cm = col & 63;
        if (m == 2) {
#pragma unroll
            for (int jj = 0; jj < 2; jj++) {
                size_t o = ((size_t)bidx * HH + cm + jj) * TT + t0;
                g_vtf[o]     = __float2half(acc[nt][jj]);
                g_vtf[o + 8] = __float2half(acc[nt][2 + jj]);
            }
        } else {
            __half* dst = (m == 1) ? g_qf : g_kf;
            *(uint32_t*)&dst[(size_t)r0 * HH + cm]       = pack2h(acc[nt][0], acc[nt][1]);
            *(uint32_t*)&dst[(size_t)(r0 + 8) * HH + cm] = pack2h(acc[nt][2], acc[nt][3]);
        }
    }
}

// ---------------------------------------------------------------------------
// Kernel C: flash attention, PURE fp16 (no lo passes).  R11/R16 structure:
// 64 queries/CTA, 4 warps, 4 CTAs/SM.  K double-buffered (2x8KB), V single
// (8KB) -> 24KB smem.  Diagonal tile peeled + causal skip.  Epilogue
// interleaved with PV per key-chunk.  exp2 softmax (scale in Wq).
// ---------------------------------------------------------------------------
#define ATTN_SMEM 24576

__global__ __launch_bounds__(128, 4) void attn_kernel(float* __restrict__ out)
{
    extern __shared__ __align__(16) char asm_[];
    const uint32_t sbase = (uint32_t)__cvta_generic_to_shared(asm_);

    const int tid = threadIdx.x, w = tid >> 5, lane = tid & 31;
    const int g = lane >> 2, t = lane & 3;
    const int c = blockIdx.x;
    const int qt = 15 - (c >> 5);               // heavy tiles first globally
    const int b  = c & 31;
    const int qrow = qt * 64 + w * 16 + g;

    const int brow = ((lane >> 4) & 1) * 8 + (lane & 7);
    const int bcol = (lane >> 3) & 1;
    const int brm  = brow & 7;
    uint32_t xoff[4];
#pragma unroll
    for (int k2 = 0; k2 < 4; k2++)
        xoff[k2] = (uint32_t)(((k2 * 2 + bcol) ^ brm) << 4);
    const uint32_t rowb = (uint32_t)(brow * 128);

    const __half* kb = g_kf + (size_t)b * TT * HH;
    const __half* vb = g_vtf + (size_t)b * HH * TT;

    auto issueK = [&](int kt, int s) {
        const uint32_t st = sbase + s * 8192;
#pragma unroll
        for (int it = 0; it < 4; it++) {
            int idx = tid + it * 128;
            int r = idx >> 3, cc = idx & 7;
            uint32_t d = (uint32_t)(r * 128 + (((cc ^ (r & 7)) << 4)));
            cp16(st + d, kb + (size_t)kt * 4096 + idx * 8);
        }
        CP_COMMIT();
    };
    auto issueV = [&](int kt) {
        const uint32_t st = sbase + 16384;
#pragma unroll
        for (int it = 0; it < 4; it++) {
            int idx = tid + it * 128;
            int r = idx >> 3, cc = idx & 7;
            uint32_t d = (uint32_t)(r * 128 + (((cc ^ (r & 7)) << 4)));
            cp16(st + d, vb + (size_t)r * TT + kt * 64 + cc * 8);
        }
        CP_COMMIT();
    };

    issueK(0, 0);
    issueV(0);

    // Persistent Q fragments (single fp16 set).
    uint32_t qf[4][4];
    {
        const __half* qp = g_qf + ((size_t)b * TT + qt * 64 + w * 16) * HH;
#pragma unroll
        for (int k2 = 0; k2 < 4; k2++) {
            int kc = k2 * 16 + 2 * t;
            qf[k2][0] = *(const uint32_t*)(qp + (size_t)g * HH + kc);
            qf[k2][1] = *(const uint32_t*)(qp + (size_t)(g + 8) * HH + kc);
            qf[k2][2] = *(const uint32_t*)(qp + (size_t)g * HH + kc + 8);
            qf[k2][3] = *(const uint32_t*)(qp + (size_t)(g + 8) * HH + kc + 8);
        }
    }

    float oacc[8][4];
#pragma unroll
    for (int i = 0; i < 8; i++)
#pragma unroll
        for (int j = 0; j < 4; j++) oacc[i][j] = 0.0f;
    float ls0 = 0.0f, ls1 = 0.0f;

    // Epilogue-for-one-chunk + PV-for-one-chunk (pure fp16).
    auto pv_chunk = [&](float sacc[8][4], int kv, int col0,
                        uint32_t stV, bool mask) {
        uint32_t pf[4];
#pragma unroll
        for (int j = 0; j < 2; j++) {
            int nt = 2 * kv + j;
            float e0, e1, e2, e3;
            if (mask) {
                int c0 = col0 + nt * 8;
                e0 = (c0     <= qrow)     ? ex2(sacc[nt][0]) : 0.0f;
                e1 = (c0 + 1 <= qrow)     ? ex2(sacc[nt][1]) : 0.0f;
                e2 = (c0     <= qrow + 8) ? ex2(sacc[nt][2]) : 0.0f;
                e3 = (c0 + 1 <= qrow + 8) ? ex2(sacc[nt][3]) : 0.0f;
            } else {
                e0 = ex2(sacc[nt][0]);
                e1 = ex2(sacc[nt][1]);
                e2 = ex2(sacc[nt][2]);
                e3 = ex2(sacc[nt][3]);
            }
            ls0 += e0 + e1;
            ls1 += e2 + e3;
            pf[j * 2]     = pack2h(e0, e1);
            pf[j * 2 + 1] = pack2h(e2, e3);
        }
#pragma unroll
        for (int p = 0; p < 4; p++) {
            uint32_t bv4[4];
            ldsm4(bv4, stV + p * 2048 + xoff[kv]);
            mmah(oacc[2 * p],     pf, bv4 + 0);
            mmah(oacc[2 * p + 1], pf, bv4 + 2);
        }
    };

    const uint32_t stVb = sbase + 16384 + rowb;

    // ---- Full (off-diagonal) tiles ----
    for (int kt = 0; kt < qt; kt++) {
        const int s = kt & 1;
        if (kt > 0) {
            __syncthreads();            // B1: PV(kt-1) reads done -> V free
            issueV(kt);
        }
        issueK(kt + 1, s ^ 1);
        CP_WAIT(2);                     // K(kt) landed
        __syncthreads();                // B2

        const uint32_t stK = sbase + s * 8192 + rowb;

        float sacc[8][4];
#pragma unroll
        for (int i = 0; i < 8; i++)
#pragma unroll
            for (int j = 0; j < 4; j++) sacc[i][j] = 0.0f;
#pragma unroll
        for (int k2 = 0; k2 < 4; k2++) {
#pragma unroll
            for (int p = 0; p < 4; p++) {
                uint32_t bk4[4];
                ldsm4(bk4, stK + p * 2048 + xoff[k2]);
                mmah(sacc[2 * p],     qf[k2], bk4 + 0);
                mmah(sacc[2 * p + 1], qf[k2], bk4 + 2);
            }
        }

        CP_WAIT(1);                     // V(kt) landed (K(kt+1) in flight)
        __syncthreads();                // B3

#pragma unroll
        for (int kv = 0; kv < 4; kv++)
            pv_chunk(sacc, kv, 0, stVb, false);
    }

    // ---- Diagonal tile (kt == qt), causal-skipped ----
    {
        const int s = qt & 1;
        if (qt > 0) {
            __syncthreads();
            issueV(qt);
        }
        CP_WAIT(1);                     // K(qt) landed
        __syncthreads();

        const uint32_t stK = sbase + s * 8192 + rowb;
        const int pmax = w + 1;

        float sacc[8][4];
#pragma unroll
        for (int i = 0; i < 8; i++)
#pragma unroll
            for (int j = 0; j < 4; j++) sacc[i][j] = 0.0f;
#pragma unroll
        for (int k2 = 0; k2 < 4; k2++) {
            for (int p = 0; p < pmax; p++) {
                uint32_t bk4[4];
                ldsm4(bk4, stK + p * 2048 + xoff[k2]);
                mmah(sacc[2 * p],     qf[k2], bk4 + 0);
                mmah(sacc[2 * p + 1], qf[k2], bk4 + 2);
            }
        }

        CP_WAIT(0);                     // V(qt) landed
        __syncthreads();

        const int col0 = qt * 64 + 2 * t;
        for (int kv = 0; kv < pmax; kv++)
            pv_chunk(sacc, kv, col0, stVb, kv == pmax - 1);
    }

    ls0 += __shfl_xor_sync(0xffffffffu, ls0, 1);
    ls0 += __shfl_xor_sync(0xffffffffu, ls0, 2);
    ls1 += __shfl_xor_sync(0xffffffffu, ls1, 1);
    ls1 += __shfl_xor_sync(0xffffffffu, ls1, 2);
    float i0 = 1.0f / ls0, i1 = 1.0f / ls1;

    float* op = out + ((size_t)b * TT + qrow) * HH;
#pragma unroll
    for (int nt = 0; nt < 8; nt++) {
        int col = nt * 8 + 2 * t;
        *(float2*)(op + col)          = make_float2(oacc[nt][0] * i0, oacc[nt][1] * i0);
        *(float2*)(op + 8 * HH + col) = make_float2(oacc[nt][2] * i1, oacc[nt][3] * i1);
    }
}

// ---------------------------------------------------------------------------
extern "C" void kernel_launch(void* const* d_in, const int* in_sizes, int n_in,
                              void* d_out, int out_size)
{
    const float* x  = (const float*)d_in[0];
    const float* Wk = (const float*)d_in[1];
    const float* Wq = (const float*)d_in[2];
    const float* Wv = (const float*)d_in[3];
    float* out = (float*)d_out;
    (void)in_sizes; (void)n_in; (void)out_size;

    splitw_kernel<<<144, 256>>>(Wk, Wq, Wv);

    cudaFuncSetAttribute(qkv_kernel,
                         cudaFuncAttributeMaxDynamicSharedMemorySize,
                         QKV_SMEM);
    qkv_kernel<<<BB * TT / 64, 256, QKV_SMEM>>>(x);

    cudaFuncSetAttribute(attn_kernel,
                         cudaFuncAttributeMaxDynamicSharedMemorySize,
                         ATTN_SMEM);
    attn_kernel<<<512, 128, ATTN_SMEM>>>(out);
}